// round 2
// baseline (speedup 1.0000x reference)
#include <cuda_runtime.h>
#include <cstdint>
#include <math.h>

// ---------------------------------------------------------------------------
// GRU cell, fused as 2 tf32 tensor-core GEMM kernels.
//   B=16384, HID=INPUT=1024, Kcat=2048.
// Kernel 1: A=concat(h,x) [B,2048] x [Wr | Wz | Wh_bot] -> r*h, z, hp scratch
//   (Wh_bot block only accumulates K in [1024,2048), i.e. x @ Wh[1024:])
// Kernel 2: (r*h) [B,1024] x Wh_top [1024,1024]; epilogue: +hp, tanh, blend.
// ---------------------------------------------------------------------------

#define BATCH   16384
#define HID     1024
#define KCAT    2048

#define BM 128
#define BN 128
#define BK 32
#define NTHREADS 256

#define A_STRIDE (BK + 4)          // floats per A smem row  (36)
#define B_STRIDE (BN + 4)          // floats per B smem row  (132)
#define A_STAGE  (BM * A_STRIDE)   // 4608 floats
#define B_STAGE  (BK * B_STRIDE)   // 4224 floats
#define SMEM_FLOATS (2 * (A_STAGE + B_STAGE))
#define SMEM_BYTES  (SMEM_FLOATS * 4)   // 70656 bytes

// Scratch (device globals -> no runtime allocation)
__device__ float g_z [BATCH * HID];   // sigmoid(z pre-act)
__device__ float g_rh[BATCH * HID];   // r * h
__device__ float g_hp[BATCH * HID];   // x @ Wh[1024:2048]

// ---------------------------------------------------------------------------

__device__ __forceinline__ uint32_t f2tf32(float f) {
    uint32_t r;
    asm("cvt.rna.tf32.f32 %0, %1;" : "=r"(r) : "f"(f));
    return r;
}

__device__ __forceinline__ void mma_tf32(float* c, const uint32_t* a, const uint32_t* b) {
    asm volatile(
        "mma.sync.aligned.m16n8k8.row.col.f32.tf32.tf32.f32 "
        "{%0,%1,%2,%3}, {%4,%5,%6,%7}, {%8,%9}, {%0,%1,%2,%3};\n"
        : "+f"(c[0]), "+f"(c[1]), "+f"(c[2]), "+f"(c[3])
        : "r"(a[0]), "r"(a[1]), "r"(a[2]), "r"(a[3]),
          "r"(b[0]), "r"(b[1]));
}

__device__ __forceinline__ void cp16(void* smem_dst, const void* gmem_src) {
    uint32_t s = (uint32_t)__cvta_generic_to_shared(smem_dst);
    asm volatile("cp.async.cg.shared.global [%0], [%1], 16;" :: "r"(s), "l"(gmem_src));
}
__device__ __forceinline__ void cp_commit() { asm volatile("cp.async.commit_group;"); }
__device__ __forceinline__ void cp_wait0()  { asm volatile("cp.async.wait_group 0;" ::: "memory"); }

__device__ __forceinline__ float sigmoidf_fast(float v) {
    return 1.0f / (1.0f + __expf(-v));
}

// ---------------------------------------------------------------------------
// MODE 1: phase-1 GEMM (gates + partial H).  MODE 2: phase-2 GEMM + final blend.
// ---------------------------------------------------------------------------
template <int MODE>
__global__ void __launch_bounds__(NTHREADS, 1)
gru_gemm_kernel(const float* __restrict__ h,
                const float* __restrict__ x,
                const float* __restrict__ Wr,
                const float* __restrict__ Wz,
                const float* __restrict__ Wh,
                float* __restrict__ out)
{
    extern __shared__ float smem[];
    float* sA = smem;                       // [2][BM][A_STRIDE]
    float* sB = smem + 2 * A_STAGE;         // [2][BK][B_STRIDE]

    const int tid    = threadIdx.x;
    const int lane   = tid & 31;
    const int wid    = tid >> 5;
    const int warp_m = wid >> 2;            // 0..1  -> 64-row band
    const int warp_n = wid & 3;             // 0..3  -> 32-col band

    // --- tile / matrix selection ---
    int mat, ntile, kstart, KT;
    const float* Bmat;
    if (MODE == 1) {
        mat    = blockIdx.x >> 3;           // 0:Wr 1:Wz 2:Wh-bottom
        ntile  = blockIdx.x & 7;
        kstart = (mat == 2) ? HID : 0;
        KT     = (KCAT - kstart) / BK;
        Bmat   = (mat == 0) ? Wr : (mat == 1) ? Wz : Wh;
    } else {
        mat    = 0;
        ntile  = blockIdx.x;                // 0..7
        kstart = 0;
        KT     = HID / BK;                  // 32
        Bmat   = Wh;                        // rows 0..1023 (k offset 0)
    }
    const int row0 = blockIdx.y * BM;
    const int col0 = ntile * BN;

    // --- stage loader ---
    auto load_stage = [&](int buf, int kt) {
        float* sAs = sA + buf * A_STAGE;
        float* sBs = sB + buf * B_STAGE;
        const int kbase = kstart + kt * BK;
        // A tile: 128 rows x 32 k, as float4 (1024 vectors / 256 threads = 4 each)
        #pragma unroll
        for (int j = 0; j < 4; j++) {
            int idx = tid + j * NTHREADS;
            int r   = idx >> 3;             // 0..127
            int k4  = idx & 7;              // 0..7  (float4 index)
            int kg  = kbase + k4 * 4;
            int rg  = row0 + r;
            const float* src;
            if (MODE == 1) {
                src = (kg < HID) ? (h + (size_t)rg * HID + kg)
                                 : (x + (size_t)rg * HID + (kg - HID));
            } else {
                src = g_rh + (size_t)rg * HID + kg;
            }
            cp16(sAs + r * A_STRIDE + k4 * 4, src);
        }
        // B tile: 32 k-rows x 128 n, as float4
        #pragma unroll
        for (int j = 0; j < 4; j++) {
            int idx = tid + j * NTHREADS;
            int k   = idx >> 5;             // 0..31
            int n4  = idx & 31;             // 0..31
            const float* src = Bmat + (size_t)(kbase + k) * HID + col0 + n4 * 4;
            cp16(sBs + k * B_STRIDE + n4 * 4, src);
        }
        cp_commit();
    };

    float acc[4][4][4];
    #pragma unroll
    for (int mt = 0; mt < 4; mt++)
        #pragma unroll
        for (int nt = 0; nt < 4; nt++)
            #pragma unroll
            for (int i = 0; i < 4; i++)
                acc[mt][nt][i] = 0.0f;

    load_stage(0, 0);

    for (int kt = 0; kt < KT; kt++) {
        cp_wait0();
        __syncthreads();
        if (kt + 1 < KT) load_stage((kt + 1) & 1, kt + 1);

        const float* sAs = sA + (kt & 1) * A_STAGE;
        const float* sBs = sB + (kt & 1) * B_STAGE;

        #pragma unroll
        for (int kk = 0; kk < 4; kk++) {
            uint32_t af[4][4], bf[4][2];
            const int krow = kk * 8 + (lane & 3);
            #pragma unroll
            for (int mt = 0; mt < 4; mt++) {
                int m0 = warp_m * 64 + mt * 16 + (lane >> 2);
                af[mt][0] = f2tf32(sAs[(m0    ) * A_STRIDE + krow    ]);
                af[mt][1] = f2tf32(sAs[(m0 + 8) * A_STRIDE + krow    ]);
                af[mt][2] = f2tf32(sAs[(m0    ) * A_STRIDE + krow + 4]);
                af[mt][3] = f2tf32(sAs[(m0 + 8) * A_STRIDE + krow + 4]);
            }
            #pragma unroll
            for (int nt = 0; nt < 4; nt++) {
                int n0 = warp_n * 32 + nt * 8 + (lane >> 2);
                bf[nt][0] = f2tf32(sBs[(krow    ) * B_STRIDE + n0]);
                bf[nt][1] = f2tf32(sBs[(krow + 4) * B_STRIDE + n0]);
            }
            #pragma unroll
            for (int mt = 0; mt < 4; mt++)
                #pragma unroll
                for (int nt = 0; nt < 4; nt++)
                    mma_tf32(acc[mt][nt], af[mt], bf[nt]);
        }
        __syncthreads();
    }

    // --- epilogue ---
    // m16n8k8 C fragment: c0,c1 -> row (lane>>2), cols 2*(lane&3)+{0,1};
    //                     c2,c3 -> row (lane>>2)+8, same cols.
    #pragma unroll
    for (int mt = 0; mt < 4; mt++) {
        #pragma unroll
        for (int nt = 0; nt < 4; nt++) {
            int r  = row0 + warp_m * 64 + mt * 16 + (lane >> 2);
            int c  = col0 + warp_n * 32 + nt * 8 + (lane & 3) * 2;
            #pragma unroll
            for (int half = 0; half < 2; half++) {
                int rr = r + half * 8;
                #pragma unroll
                for (int e = 0; e < 2; e++) {
                    float v = acc[mt][nt][half * 2 + e];
                    size_t gi = (size_t)rr * HID + (c + e);   // local col already in [0,HID)
                    if (MODE == 1) {
                        if (mat == 0) {
                            float rg = sigmoidf_fast(v);
                            g_rh[gi] = rg * h[gi];
                        } else if (mat == 1) {
                            g_z[gi] = sigmoidf_fast(v);
                        } else {
                            g_hp[gi] = v;
                        }
                    } else {
                        float pre = v + g_hp[gi];
                        float ht  = tanhf(pre);
                        float z   = g_z[gi];
                        float hv  = h[gi];
                        out[gi]   = hv + z * (ht - hv);
                    }
                }
            }
        }
    }
}

// ---------------------------------------------------------------------------

extern "C" void kernel_launch(void* const* d_in, const int* in_sizes, int n_in,
                              void* d_out, int out_size)
{
    const float* h  = (const float*)d_in[0];
    const float* x  = (const float*)d_in[1];
    const float* Wr = (const float*)d_in[2];
    const float* Wz = (const float*)d_in[3];
    const float* Wh = (const float*)d_in[4];
    float* out = (float*)d_out;

    cudaFuncSetAttribute(gru_gemm_kernel<1>,
                         cudaFuncAttributeMaxDynamicSharedMemorySize, SMEM_BYTES);
    cudaFuncSetAttribute(gru_gemm_kernel<2>,
                         cudaFuncAttributeMaxDynamicSharedMemorySize, SMEM_BYTES);

    // Phase 1: N = 3072 (Wr | Wz | Wh-bottom), n-fastest rasterization for L2 reuse.
    dim3 grid1(24, BATCH / BM);
    gru_gemm_kernel<1><<<grid1, NTHREADS, SMEM_BYTES>>>(h, x, Wr, Wz, Wh, out);

    // Phase 2: (r*h) @ Wh_top, K = 1024, then blend.
    dim3 grid2(8, BATCH / BM);
    gru_gemm_kernel<2><<<grid2, NTHREADS, SMEM_BYTES>>>(h, x, Wr, Wz, Wh, out);
}

// round 4
// speedup vs baseline: 1.1933x; 1.1933x over previous
#include <cuda_runtime.h>
#include <cstdint>
#include <math.h>

// ---------------------------------------------------------------------------
// GRU cell, legacy mma.sync tf32 path (tcgen05 unavailable: harness PTX target
// is plain sm_103, 'a'-features rejected by ptxas — proven in R3).
//
// Prep A : g_A = tf32_rna(concat(h,x))            [16384 x 2048]
// Prep W : g_W[g] = tf32_rna(W_r / W_z / W_h)     [2048 x 1024] each
// Phase1 : fused 3-gate GEMM per CTA (64x64 per gate, shared A fragments):
//            r = sigmoid(.), z = sigmoid(.), hp = x @ Wh[1024:]
//          writes g_rh = rna(r*h), g_z, g_hp
// Phase2 : g_rh @ Wh[:1024] (128x128 tiles), epilogue tanh + blend -> out
// No CVT in any mainloop: all operands pre-rounded to tf32-valued fp32.
// ---------------------------------------------------------------------------

#define BATCH   16384
#define HID     1024
#define KCAT    2048
#define BK      32
#define NST     3

// ---- phase 1 geometry: 64 x 64 x 3 gates, 256 threads (8 warps, 2m x 4n) ----
#define BM1 64
#define BN1 64
#define A1_STRIDE 36                    // floats
#define B1_STRIDE 72                    // floats (8*l3+l2 bank pattern)
#define A1_STAGE (BM1 * A1_STRIDE)      // 2304 floats
#define B1_STAGE (3 * BK * B1_STRIDE)   // 6912 floats
#define S1_STAGE ((A1_STAGE + B1_STAGE) * 4)   // 36864 bytes
#define SMEM1_TOTAL (NST * S1_STAGE)           // 110592

// ---- phase 2 geometry: 128 x 128, 256 threads (8 warps, 2m x 4n) ----
#define BM2 128
#define BN2 128
#define A2_STRIDE 36
#define B2_STRIDE 136
#define A2_STAGE (BM2 * A2_STRIDE)      // 4608 floats
#define B2_STAGE (BK * B2_STRIDE)       // 4352 floats
#define S2_STAGE ((A2_STAGE + B2_STAGE) * 4)   // 35840 bytes
#define SMEM2_TOTAL (NST * S2_STAGE)           // 107520

// -------------------------- device scratch ---------------------------------
__device__ float g_A [BATCH * KCAT];   // tf32-rounded concat(h,x)
__device__ float g_W [3][KCAT * HID];  // tf32-rounded W_r, W_z, W_h
__device__ float g_z [BATCH * HID];
__device__ float g_rh[BATCH * HID];    // tf32-rounded r*h
__device__ float g_hp[BATCH * HID];

// -------------------------- helpers ----------------------------------------
__device__ __forceinline__ float rna_tf32(float f) {
    uint32_t r;
    asm("cvt.rna.tf32.f32 %0, %1;" : "=r"(r) : "f"(f));
    return __uint_as_float(r);
}
__device__ __forceinline__ void mma_tf32(float* c, const uint32_t* a, const uint32_t* b) {
    asm volatile(
        "mma.sync.aligned.m16n8k8.row.col.f32.tf32.tf32.f32 "
        "{%0,%1,%2,%3}, {%4,%5,%6,%7}, {%8,%9}, {%0,%1,%2,%3};\n"
        : "+f"(c[0]), "+f"(c[1]), "+f"(c[2]), "+f"(c[3])
        : "r"(a[0]), "r"(a[1]), "r"(a[2]), "r"(a[3]),
          "r"(b[0]), "r"(b[1]));
}
__device__ __forceinline__ void cp16(void* smem_dst, const void* gmem_src) {
    uint32_t s = (uint32_t)__cvta_generic_to_shared(smem_dst);
    asm volatile("cp.async.cg.shared.global [%0], [%1], 16;" :: "r"(s), "l"(gmem_src));
}
__device__ __forceinline__ void cp_commit() { asm volatile("cp.async.commit_group;"); }
template <int N>
__device__ __forceinline__ void cp_wait() { asm volatile("cp.async.wait_group %0;" :: "n"(N) : "memory"); }
__device__ __forceinline__ float sigmoidf_fast(float v) { return 1.0f / (1.0f + __expf(-v)); }
__device__ __forceinline__ uint32_t fbits(float f) { return __float_as_uint(f); }

// ---------------------------------------------------------------------------
// Prep kernels: elementwise tf32 rounding (and concat for A)
// ---------------------------------------------------------------------------
__global__ void prep_concat_kernel(const float* __restrict__ h,
                                   const float* __restrict__ x)
{
    // one float4 per thread iteration over [BATCH][KCAT]
    size_t n4 = (size_t)BATCH * KCAT / 4;
    for (size_t i = (size_t)blockIdx.x * blockDim.x + threadIdx.x;
         i < n4; i += (size_t)gridDim.x * blockDim.x) {
        size_t e = i * 4;
        size_t row = e >> 11;            // / KCAT
        size_t col = e & (KCAT - 1);
        const float* src = (col < HID) ? (h + row * HID + col)
                                       : (x + row * HID + (col - HID));
        float4 v = *(const float4*)src;
        v.x = rna_tf32(v.x); v.y = rna_tf32(v.y);
        v.z = rna_tf32(v.z); v.w = rna_tf32(v.w);
        ((float4*)g_A)[i] = v;
    }
}

__global__ void prep_weights_kernel(const float* __restrict__ Wr,
                                    const float* __restrict__ Wz,
                                    const float* __restrict__ Wh)
{
    const float* src[3] = {Wr, Wz, Wh};
    size_t n4 = (size_t)KCAT * HID / 4;
    for (size_t i = (size_t)blockIdx.x * blockDim.x + threadIdx.x;
         i < 3 * n4; i += (size_t)gridDim.x * blockDim.x) {
        int g = (int)(i / n4);
        size_t j = i - (size_t)g * n4;
        float4 v = ((const float4*)src[g])[j];
        v.x = rna_tf32(v.x); v.y = rna_tf32(v.y);
        v.z = rna_tf32(v.z); v.w = rna_tf32(v.w);
        ((float4*)g_W[g])[j] = v;
    }
}

// ---------------------------------------------------------------------------
// Phase 1: fused 3-gate GEMM. Tile 64 rows x 64 cols per gate.
// Gates 0 (r), 1 (z): K = 0..2047.  Gate 2 (h-bottom): K = 1024..2047.
// ---------------------------------------------------------------------------
__global__ void __launch_bounds__(256, 2)
gru_phase1(const float* __restrict__ h)
{
    extern __shared__ float smem[];
    const int tid    = threadIdx.x;
    const int lane   = tid & 31;
    const int wid    = tid >> 5;
    const int warp_m = wid & 1;          // 0..1 -> 32-row band
    const int warp_n = wid >> 1;         // 0..3 -> 16-col band
    const int col0   = blockIdx.x * BN1;
    const int row0   = blockIdx.y * BM1;
    const int KT     = KCAT / BK;        // 64

    auto load_stage = [&](int kt) {
        float* sAs = smem + (kt % NST) * (S1_STAGE / 4);
        float* sBs = sAs + A1_STAGE;
        const int kbase = kt * BK;
        // A: 64 rows x 8 chunks = 512 chunks
        #pragma unroll
        for (int j = 0; j < 2; j++) {
            int idx = tid + j * 256;
            int r = idx >> 3, c = idx & 7;
            cp16(sAs + r * A1_STRIDE + c * 4,
                 g_A + (size_t)(row0 + r) * KCAT + kbase + c * 4);
        }
        // B: per gate 32 k-rows x 16 chunks = 512 chunks
        #pragma unroll
        for (int g = 0; g < 3; g++) {
            if (g == 2 && kt < 32) continue;
            #pragma unroll
            for (int j = 0; j < 2; j++) {
                int idx = tid + j * 256;
                int r = idx >> 4, c = idx & 15;
                cp16(sBs + (g * BK + r) * B1_STRIDE + c * 4,
                     g_W[g] + (size_t)(kbase + r) * HID + col0 + c * 4);
            }
        }
        cp_commit();
    };

    float acc[3][2][2][4];
    #pragma unroll
    for (int g = 0; g < 3; g++)
        #pragma unroll
        for (int mt = 0; mt < 2; mt++)
            #pragma unroll
            for (int nt = 0; nt < 2; nt++)
                #pragma unroll
                for (int i = 0; i < 4; i++)
                    acc[g][mt][nt][i] = 0.0f;

    load_stage(0);
    load_stage(1);

    for (int kt = 0; kt < KT; kt++) {
        if (kt < KT - 1) cp_wait<1>(); else cp_wait<0>();
        __syncthreads();
        if (kt + 2 < KT) load_stage(kt + 2);

        const float* sAs = smem + (kt % NST) * (S1_STAGE / 4);
        const float* sBs = sAs + A1_STAGE;
        const bool g2 = (kt >= 32);

        #pragma unroll
        for (int kk = 0; kk < 4; kk++) {
            const int krow = kk * 8 + (lane & 3);
            uint32_t af[2][4];
            #pragma unroll
            for (int mt = 0; mt < 2; mt++) {
                int m0 = warp_m * 32 + mt * 16 + (lane >> 2);
                af[mt][0] = fbits(sAs[(m0    ) * A1_STRIDE + krow    ]);
                af[mt][1] = fbits(sAs[(m0 + 8) * A1_STRIDE + krow    ]);
                af[mt][2] = fbits(sAs[(m0    ) * A1_STRIDE + krow + 4]);
                af[mt][3] = fbits(sAs[(m0 + 8) * A1_STRIDE + krow + 4]);
            }
            #pragma unroll
            for (int g = 0; g < 3; g++) {
                if (g == 2 && !g2) continue;
                uint32_t bf[2][2];
                #pragma unroll
                for (int nt = 0; nt < 2; nt++) {
                    int n0 = warp_n * 16 + nt * 8 + (lane >> 2);
                    bf[nt][0] = fbits(sBs[(g * BK + krow    ) * B1_STRIDE + n0]);
                    bf[nt][1] = fbits(sBs[(g * BK + krow + 4) * B1_STRIDE + n0]);
                }
                #pragma unroll
                for (int mt = 0; mt < 2; mt++)
                    #pragma unroll
                    for (int nt = 0; nt < 2; nt++)
                        mma_tf32(acc[g][mt][nt], af[mt], bf[nt]);
            }
        }
        __syncthreads();
    }

    // epilogue: c0,c1 -> (row, 2*(lane&3)+{0,1}); c2,c3 -> row+8
    #pragma unroll
    for (int mt = 0; mt < 2; mt++) {
        #pragma unroll
        for (int nt = 0; nt < 2; nt++) {
            int r = row0 + warp_m * 32 + mt * 16 + (lane >> 2);
            int c = col0 + warp_n * 16 + nt * 8 + (lane & 3) * 2;
            #pragma unroll
            for (int half = 0; half < 2; half++) {
                int rr = r + half * 8;
                size_t gi = (size_t)rr * HID + c;
                // gate 0: r -> g_rh (tf32-rounded)
                {
                    float2 hv = *(const float2*)(h + gi);
                    float2 o;
                    o.x = rna_tf32(sigmoidf_fast(acc[0][mt][nt][half*2+0]) * hv.x);
                    o.y = rna_tf32(sigmoidf_fast(acc[0][mt][nt][half*2+1]) * hv.y);
                    *(float2*)(g_rh + gi) = o;
                }
                // gate 1: z
                {
                    float2 o;
                    o.x = sigmoidf_fast(acc[1][mt][nt][half*2+0]);
                    o.y = sigmoidf_fast(acc[1][mt][nt][half*2+1]);
                    *(float2*)(g_z + gi) = o;
                }
                // gate 2: hp
                {
                    float2 o;
                    o.x = acc[2][mt][nt][half*2+0];
                    o.y = acc[2][mt][nt][half*2+1];
                    *(float2*)(g_hp + gi) = o;
                }
            }
        }
    }
}

// ---------------------------------------------------------------------------
// Phase 2: (r*h) @ Wh[:1024].  Tile 128 x 128, K = 1024.
// ---------------------------------------------------------------------------
__global__ void __launch_bounds__(256, 2)
gru_phase2(const float* __restrict__ h, float* __restrict__ out)
{
    extern __shared__ float smem[];
    const int tid    = threadIdx.x;
    const int lane   = tid & 31;
    const int wid    = tid >> 5;
    const int warp_m = wid >> 2;         // 0..1 -> 64-row band
    const int warp_n = wid & 3;          // 0..3 -> 32-col band
    const int col0   = blockIdx.x * BN2;
    const int row0   = blockIdx.y * BM2;
    const int KT     = HID / BK;         // 32

    auto load_stage = [&](int kt) {
        float* sAs = smem + (kt % NST) * (S2_STAGE / 4);
        float* sBs = sAs + A2_STAGE;
        const int kbase = kt * BK;
        #pragma unroll
        for (int j = 0; j < 4; j++) {    // A: 128 x 8 chunks
            int idx = tid + j * 256;
            int r = idx >> 3, c = idx & 7;
            cp16(sAs + r * A2_STRIDE + c * 4,
                 g_rh + (size_t)(row0 + r) * HID + kbase + c * 4);
        }
        #pragma unroll
        for (int j = 0; j < 4; j++) {    // B: 32 x 32 chunks
            int idx = tid + j * 256;
            int r = idx >> 5, c = idx & 31;
            cp16(sBs + r * B2_STRIDE + c * 4,
                 g_W[2] + (size_t)(kbase + r) * HID + col0 + c * 4);
        }
        cp_commit();
    };

    float acc[4][4][4];
    #pragma unroll
    for (int mt = 0; mt < 4; mt++)
        #pragma unroll
        for (int nt = 0; nt < 4; nt++)
            #pragma unroll
            for (int i = 0; i < 4; i++)
                acc[mt][nt][i] = 0.0f;

    load_stage(0);
    load_stage(1);

    for (int kt = 0; kt < KT; kt++) {
        if (kt < KT - 1) cp_wait<1>(); else cp_wait<0>();
        __syncthreads();
        if (kt + 2 < KT) load_stage(kt + 2);

        const float* sAs = smem + (kt % NST) * (S2_STAGE / 4);
        const float* sBs = sAs + A2_STAGE;

        #pragma unroll
        for (int kk = 0; kk < 4; kk++) {
            const int krow = kk * 8 + (lane & 3);
            uint32_t af[4][4], bf[4][2];
            #pragma unroll
            for (int mt = 0; mt < 4; mt++) {
                int m0 = warp_m * 64 + mt * 16 + (lane >> 2);
                af[mt][0] = fbits(sAs[(m0    ) * A2_STRIDE + krow    ]);
                af[mt][1] = fbits(sAs[(m0 + 8) * A2_STRIDE + krow    ]);
                af[mt][2] = fbits(sAs[(m0    ) * A2_STRIDE + krow + 4]);
                af[mt][3] = fbits(sAs[(m0 + 8) * A2_STRIDE + krow + 4]);
            }
            #pragma unroll
            for (int nt = 0; nt < 4; nt++) {
                int n0 = warp_n * 32 + nt * 8 + (lane >> 2);
                bf[nt][0] = fbits(sBs[(krow    ) * B2_STRIDE + n0]);
                bf[nt][1] = fbits(sBs[(krow + 4) * B2_STRIDE + n0]);
            }
            #pragma unroll
            for (int mt = 0; mt < 4; mt++)
                #pragma unroll
                for (int nt = 0; nt < 4; nt++)
                    mma_tf32(acc[mt][nt], af[mt], bf[nt]);
        }
        __syncthreads();
    }

    // epilogue: h_tilde = tanh(v + hp); out = h + z*(h_tilde - h)
    #pragma unroll
    for (int mt = 0; mt < 4; mt++) {
        #pragma unroll
        for (int nt = 0; nt < 4; nt++) {
            int r = row0 + warp_m * 64 + mt * 16 + (lane >> 2);
            int c = col0 + warp_n * 32 + nt * 8 + (lane & 3) * 2;
            #pragma unroll
            for (int half = 0; half < 2; half++) {
                int rr = r + half * 8;
                size_t gi = (size_t)rr * HID + c;
                float2 hp2 = *(const float2*)(g_hp + gi);
                float2 z2  = *(const float2*)(g_z  + gi);
                float2 hv2 = *(const float2*)(h    + gi);
                float t0 = tanhf(acc[mt][nt][half*2+0] + hp2.x);
                float t1 = tanhf(acc[mt][nt][half*2+1] + hp2.y);
                float2 o;
                o.x = hv2.x + z2.x * (t0 - hv2.x);
                o.y = hv2.y + z2.y * (t1 - hv2.y);
                *(float2*)(out + gi) = o;
            }
        }
    }
}

// ---------------------------------------------------------------------------

extern "C" void kernel_launch(void* const* d_in, const int* in_sizes, int n_in,
                              void* d_out, int out_size)
{
    const float* h  = (const float*)d_in[0];
    const float* x  = (const float*)d_in[1];
    const float* Wr = (const float*)d_in[2];
    const float* Wz = (const float*)d_in[3];
    const float* Wh = (const float*)d_in[4];
    float* out = (float*)d_out;

    cudaFuncSetAttribute(gru_phase1, cudaFuncAttributeMaxDynamicSharedMemorySize, SMEM1_TOTAL);
    cudaFuncSetAttribute(gru_phase2, cudaFuncAttributeMaxDynamicSharedMemorySize, SMEM2_TOTAL);

    prep_concat_kernel <<<2048, 256>>>(h, x);
    prep_weights_kernel<<<1024, 256>>>(Wr, Wz, Wh);

    // Phase 1: grid x-fastest so column-CTAs share the A row panel in L2.
    dim3 g1(HID / BN1, BATCH / BM1);      // (16, 256)
    gru_phase1<<<g1, 256, SMEM1_TOTAL>>>(h);

    dim3 g2(HID / BN2, BATCH / BM2);      // (8, 128)
    gru_phase2<<<g2, 256, SMEM2_TOTAL>>>(h, out);
}

// round 5
// speedup vs baseline: 2.2664x; 1.8993x over previous
#include <cuda_runtime.h>
#include <cuda_fp16.h>
#include <cstdint>
#include <math.h>

// ---------------------------------------------------------------------------
// GRU cell, legacy mma path (tcgen05 rejected by harness PTX target sm_103).
// R5: fp16 operands (same 11-bit mantissa as tf32 -> same accuracy), fp32
// accumulate, ldmatrix fragment loads.
//
// Prep A : g_A  = half(concat(h,x))               [16384 x 2048]
// Prep W : g_Wt[g][n][k] = half(W_g[k][n])        [1024 x 2048] each (K-major)
// Phase1 : virtual N=3072 GEMM over g_A x {Wr|Wz|Wh_bot}; epilogue writes
//          g_rh = half(sigmoid(r)*h), g_z, g_hp  (Wh block: K in [1024,2048))
// Phase2 : g_rh @ Wh[:1024]; epilogue tanh + blend -> out
// ---------------------------------------------------------------------------

#define BATCH   16384
#define HID     1024
#define KCAT    2048
#define BK      32            // k halves per stage (2 x k16 MMA steps)
#define NST     3

#define BM 128
#define BN 128
#define RS 40                               // smem row stride in halves (80 B)
#define A_STAGE_B (BM * RS * 2)             // 10240 B
#define B_STAGE_B (BN * RS * 2)             // 10240 B
#define STAGE_B   (A_STAGE_B + B_STAGE_B)   // 20480 B
#define SMEM_TOTAL (NST * STAGE_B)          // 61440 B

// -------------------------- device scratch ---------------------------------
__device__ __half g_A [BATCH * KCAT];
__device__ __half g_Wt[3][HID * KCAT];   // [n][k]
__device__ __half g_rh[BATCH * HID];
__device__ float  g_z [BATCH * HID];
__device__ float  g_hp[BATCH * HID];

// -------------------------- helpers ----------------------------------------
__device__ __forceinline__ void mma_f16(float* c, const uint32_t* a, const uint32_t* b) {
    asm volatile(
        "mma.sync.aligned.m16n8k16.row.col.f32.f16.f16.f32 "
        "{%0,%1,%2,%3}, {%4,%5,%6,%7}, {%8,%9}, {%0,%1,%2,%3};\n"
        : "+f"(c[0]), "+f"(c[1]), "+f"(c[2]), "+f"(c[3])
        : "r"(a[0]), "r"(a[1]), "r"(a[2]), "r"(a[3]),
          "r"(b[0]), "r"(b[1]));
}
__device__ __forceinline__ void ldsm4(uint32_t* r, uint32_t addr) {
    asm volatile("ldmatrix.sync.aligned.m8n8.x4.shared.b16 {%0,%1,%2,%3}, [%4];"
                 : "=r"(r[0]), "=r"(r[1]), "=r"(r[2]), "=r"(r[3]) : "r"(addr));
}
__device__ __forceinline__ void cp16(uint32_t smem_dst, const void* gsrc) {
    asm volatile("cp.async.cg.shared.global [%0], [%1], 16;" :: "r"(smem_dst), "l"(gsrc));
}
__device__ __forceinline__ void cp_commit() { asm volatile("cp.async.commit_group;"); }
template <int N>
__device__ __forceinline__ void cp_wait() { asm volatile("cp.async.wait_group %0;" :: "n"(N) : "memory"); }
__device__ __forceinline__ float sigmoidf_fast(float v) { return 1.0f / (1.0f + __expf(-v)); }

// ---------------------------------------------------------------------------
// Prep kernels
// ---------------------------------------------------------------------------
__global__ void prep_concat_kernel(const float* __restrict__ h,
                                   const float* __restrict__ x)
{
    size_t n8 = (size_t)BATCH * KCAT / 8;
    for (size_t i = (size_t)blockIdx.x * blockDim.x + threadIdx.x;
         i < n8; i += (size_t)gridDim.x * blockDim.x) {
        size_t e   = i * 8;
        size_t row = e >> 11;
        size_t col = e & (KCAT - 1);
        const float* src = (col < HID) ? (h + row * HID + col)
                                       : (x + row * HID + (col - HID));
        float4 v0 = ((const float4*)src)[0];
        float4 v1 = ((const float4*)src)[1];
        __half2 o[4];
        o[0] = __float22half2_rn(make_float2(v0.x, v0.y));
        o[1] = __float22half2_rn(make_float2(v0.z, v0.w));
        o[2] = __float22half2_rn(make_float2(v1.x, v1.y));
        o[3] = __float22half2_rn(make_float2(v1.z, v1.w));
        ((uint4*)g_A)[i] = *(uint4*)o;
    }
}

// transpose + convert: g_Wt[g][n][k] = half(W_g[k][n])
__global__ void prep_weights_kernel(const float* __restrict__ Wr,
                                    const float* __restrict__ Wz,
                                    const float* __restrict__ Wh)
{
    __shared__ float t[32][33];
    const float* src = (blockIdx.z == 0) ? Wr : (blockIdx.z == 1) ? Wz : Wh;
    __half* dst = g_Wt[blockIdx.z];
    int tx = threadIdx.x, ty = threadIdx.y;
    int c0 = blockIdx.x * 32;   // n
    int r0 = blockIdx.y * 32;   // k
    #pragma unroll
    for (int j = 0; j < 32; j += 8)
        t[ty + j][tx] = src[(size_t)(r0 + ty + j) * HID + c0 + tx];
    __syncthreads();
    #pragma unroll
    for (int j = 0; j < 32; j += 8)
        dst[(size_t)(c0 + ty + j) * KCAT + r0 + tx] = __float2half_rn(t[tx][ty + j]);
}

// ---------------------------------------------------------------------------
// Unified GEMM.  MODE 1: gates (A = g_A, stride KCAT).  MODE 2: h-tilde.
// ---------------------------------------------------------------------------
template <int MODE>
__global__ void __launch_bounds__(256, 2)
gru_gemm(const float* __restrict__ h, float* __restrict__ out)
{
    extern __shared__ char smem[];
    const uint32_t sbase = (uint32_t)__cvta_generic_to_shared(smem);
    const int tid    = threadIdx.x;
    const int lane   = tid & 31;
    const int wid    = tid >> 5;
    const int warp_m = wid >> 2;         // 0..1 -> 64-row band
    const int warp_n = wid & 3;          // 0..3 -> 32-col band

    int mat, kstart, KT, col0;
    const __half* Bmat;
    const __half* Amat;
    int astride;
    if (MODE == 1) {
        mat    = blockIdx.x >> 3;
        col0   = (blockIdx.x & 7) * BN;
        kstart = (mat == 2) ? HID : 0;
        KT     = (KCAT - kstart) / BK;
        Bmat   = g_Wt[mat];
        Amat   = g_A;  astride = KCAT;
    } else {
        mat    = 0;
        col0   = blockIdx.x * BN;
        kstart = 0;
        KT     = HID / BK;               // 32
        Bmat   = g_Wt[2];
        Amat   = g_rh; astride = HID;
    }
    const int row0 = blockIdx.y * BM;

    auto load_stage = [&](int kt) {
        const uint32_t so = sbase + (kt % NST) * STAGE_B;
        const int kbase = kstart + kt * BK;
        #pragma unroll
        for (int j = 0; j < 2; j++) {        // A: 128 rows x 4 16B-chunks
            int idx = tid + j * 256;
            int r = idx >> 2, c = idx & 3;
            cp16(so + r * (RS * 2) + c * 16,
                 Amat + (size_t)(row0 + r) * astride + kbase + c * 8);
        }
        #pragma unroll
        for (int j = 0; j < 2; j++) {        // B: 128 n-rows x 4 chunks
            int idx = tid + j * 256;
            int r = idx >> 2, c = idx & 3;
            cp16(so + A_STAGE_B + r * (RS * 2) + c * 16,
                 Bmat + (size_t)(col0 + r) * KCAT + kbase + c * 8);
        }
        cp_commit();
    };

    // per-thread ldmatrix offsets (bytes within stage)
    // A: row = warp_m*64 + mt*16 + (lane&15); +16B when lane>=16 (k upper 8)
    uint32_t a_off[4];
    #pragma unroll
    for (int mt = 0; mt < 4; mt++)
        a_off[mt] = (warp_m * 64 + mt * 16 + (lane & 15)) * (RS * 2)
                  + ((lane >> 4) & 1) * 16;
    // B: n-row = warp_n*32 + nt2*16 + (lane&7) + 8*(lane>=16); +16B when (lane>>3)&1
    uint32_t b_off[2];
    #pragma unroll
    for (int nt2 = 0; nt2 < 2; nt2++)
        b_off[nt2] = A_STAGE_B
                   + (warp_n * 32 + nt2 * 16 + (lane & 7) + ((lane >> 4) & 1) * 8) * (RS * 2)
                   + ((lane >> 3) & 1) * 16;

    float acc[4][4][4];
    #pragma unroll
    for (int mt = 0; mt < 4; mt++)
        #pragma unroll
        for (int nt = 0; nt < 4; nt++)
            #pragma unroll
            for (int i = 0; i < 4; i++)
                acc[mt][nt][i] = 0.0f;

    load_stage(0);
    load_stage(1);

    for (int kt = 0; kt < KT; kt++) {
        if (kt < KT - 1) cp_wait<1>(); else cp_wait<0>();
        __syncthreads();
        if (kt + 2 < KT) load_stage(kt + 2);

        const uint32_t so = sbase + (kt % NST) * STAGE_B;
        #pragma unroll
        for (int ks = 0; ks < 2; ks++) {     // two k16 steps per stage
            uint32_t a[4][4], b[2][4];
            #pragma unroll
            for (int mt = 0; mt < 4; mt++)
                ldsm4(a[mt], so + a_off[mt] + ks * 32);
            #pragma unroll
            for (int nt2 = 0; nt2 < 2; nt2++)
                ldsm4(b[nt2], so + b_off[nt2] + ks * 32);
            #pragma unroll
            for (int mt = 0; mt < 4; mt++)
                #pragma unroll
                for (int nt = 0; nt < 4; nt++)
                    mma_f16(acc[mt][nt], a[mt], &b[nt >> 1][(nt & 1) * 2]);
        }
        __syncthreads();
    }

    // ---- epilogue ----
    // C frag: c0,c1 -> (row g, col 2c+{0,1}); c2,c3 -> row g+8.
    #pragma unroll
    for (int mt = 0; mt < 4; mt++) {
        #pragma unroll
        for (int nt = 0; nt < 4; nt++) {
            int r = row0 + warp_m * 64 + mt * 16 + (lane >> 2);
            int c = col0 + warp_n * 32 + nt * 8 + (lane & 3) * 2;
            #pragma unroll
            for (int half_i = 0; half_i < 2; half_i++) {
                int rr = r + half_i * 8;
                size_t gi = (size_t)rr * HID + c;
                float v0 = acc[mt][nt][half_i * 2 + 0];
                float v1 = acc[mt][nt][half_i * 2 + 1];
                if (MODE == 1) {
                    if (mat == 0) {
                        float2 hv = *(const float2*)(h + gi);
                        __half2 o = __float22half2_rn(make_float2(
                            sigmoidf_fast(v0) * hv.x, sigmoidf_fast(v1) * hv.y));
                        *(__half2*)(g_rh + gi) = o;
                    } else if (mat == 1) {
                        float2 o = make_float2(sigmoidf_fast(v0), sigmoidf_fast(v1));
                        *(float2*)(g_z + gi) = o;
                    } else {
                        *(float2*)(g_hp + gi) = make_float2(v0, v1);
                    }
                } else {
                    float2 hp2 = *(const float2*)(g_hp + gi);
                    float2 z2  = *(const float2*)(g_z  + gi);
                    float2 hv2 = *(const float2*)(h    + gi);
                    float t0 = tanhf(v0 + hp2.x);
                    float t1 = tanhf(v1 + hp2.y);
                    float2 o;
                    o.x = hv2.x + z2.x * (t0 - hv2.x);
                    o.y = hv2.y + z2.y * (t1 - hv2.y);
                    *(float2*)(out + gi) = o;
                }
            }
        }
    }
}

// ---------------------------------------------------------------------------

extern "C" void kernel_launch(void* const* d_in, const int* in_sizes, int n_in,
                              void* d_out, int out_size)
{
    const float* h  = (const float*)d_in[0];
    const float* x  = (const float*)d_in[1];
    const float* Wr = (const float*)d_in[2];
    const float* Wz = (const float*)d_in[3];
    const float* Wh = (const float*)d_in[4];
    float* out = (float*)d_out;

    cudaFuncSetAttribute(gru_gemm<1>, cudaFuncAttributeMaxDynamicSharedMemorySize, SMEM_TOTAL);
    cudaFuncSetAttribute(gru_gemm<2>, cudaFuncAttributeMaxDynamicSharedMemorySize, SMEM_TOTAL);

    prep_concat_kernel <<<2048, 256>>>(h, x);
    dim3 gT(HID / 32, KCAT / 32, 3);
    prep_weights_kernel<<<gT, dim3(32, 8)>>>(Wr, Wz, Wh);

    // Phase 1: x-fastest raster -> the 24 column-CTAs of one row panel share A in L2.
    dim3 g1(24, BATCH / BM);
    gru_gemm<1><<<g1, 256, SMEM_TOTAL>>>(h, out);

    dim3 g2(HID / BN, BATCH / BM);   // (8, 128)
    gru_gemm<2><<<g2, 256, SMEM_TOTAL>>>(h, out);
}

// round 6
// speedup vs baseline: 2.4566x; 1.0839x over previous
#include <cuda_runtime.h>
#include <cuda_fp16.h>
#include <cstdint>
#include <math.h>

// ---------------------------------------------------------------------------
// GRU cell, legacy mma path (tcgen05 rejected by harness PTX target sm_103).
// R6: BK=64 deep stages, single barrier per k-iteration, fp16 ldmatrix+mma.
//
// Prep A : g_A  = half(concat(h,x))               [16384 x 2048]
// Prep W : g_Wt[g][n][k] = half(W_g[k][n])        [1024 x 2048] each (K-major)
// Phase1 : virtual N=3072 GEMM; epilogue -> g_rh (half), g_z, g_hp
// Phase2 : g_rh @ Wh[:1024]; epilogue tanh + blend -> out
// ---------------------------------------------------------------------------

#define BATCH   16384
#define HID     1024
#define KCAT    2048
#define BK      64            // k halves per stage (4 x k16 MMA steps)
#define NST     3

#define BM 128
#define BN 128
#define RS 72                               // smem row stride in halves (144 B)
#define A_STAGE_B (BM * RS * 2)             // 18432 B
#define B_STAGE_B (BN * RS * 2)             // 18432 B
#define STAGE_B   (A_STAGE_B + B_STAGE_B)   // 36864 B
#define SMEM_TOTAL (NST * STAGE_B)          // 110592 B

// -------------------------- device scratch ---------------------------------
__device__ __half g_A [BATCH * KCAT];
__device__ __half g_Wt[3][HID * KCAT];   // [n][k]
__device__ __half g_rh[BATCH * HID];
__device__ float  g_z [BATCH * HID];
__device__ float  g_hp[BATCH * HID];

// -------------------------- helpers ----------------------------------------
__device__ __forceinline__ void mma_f16(float* c, const uint32_t* a, const uint32_t* b) {
    asm volatile(
        "mma.sync.aligned.m16n8k16.row.col.f32.f16.f16.f32 "
        "{%0,%1,%2,%3}, {%4,%5,%6,%7}, {%8,%9}, {%0,%1,%2,%3};\n"
        : "+f"(c[0]), "+f"(c[1]), "+f"(c[2]), "+f"(c[3])
        : "r"(a[0]), "r"(a[1]), "r"(a[2]), "r"(a[3]),
          "r"(b[0]), "r"(b[1]));
}
__device__ __forceinline__ void ldsm4(uint32_t* r, uint32_t addr) {
    asm volatile("ldmatrix.sync.aligned.m8n8.x4.shared.b16 {%0,%1,%2,%3}, [%4];"
                 : "=r"(r[0]), "=r"(r[1]), "=r"(r[2]), "=r"(r[3]) : "r"(addr));
}
__device__ __forceinline__ void cp16(uint32_t smem_dst, const void* gsrc) {
    asm volatile("cp.async.cg.shared.global [%0], [%1], 16;" :: "r"(smem_dst), "l"(gsrc));
}
__device__ __forceinline__ void cp_commit() { asm volatile("cp.async.commit_group;"); }
template <int N>
__device__ __forceinline__ void cp_wait() { asm volatile("cp.async.wait_group %0;" :: "n"(N) : "memory"); }
__device__ __forceinline__ float sigmoidf_fast(float v) { return 1.0f / (1.0f + __expf(-v)); }

// ---------------------------------------------------------------------------
// Prep kernels
// ---------------------------------------------------------------------------
__global__ void prep_concat_kernel(const float* __restrict__ h,
                                   const float* __restrict__ x)
{
    size_t n8 = (size_t)BATCH * KCAT / 8;
    for (size_t i = (size_t)blockIdx.x * blockDim.x + threadIdx.x;
         i < n8; i += (size_t)gridDim.x * blockDim.x) {
        size_t e   = i * 8;
        size_t row = e >> 11;
        size_t col = e & (KCAT - 1);
        const float* src = (col < HID) ? (h + row * HID + col)
                                       : (x + row * HID + (col - HID));
        float4 v0 = ((const float4*)src)[0];
        float4 v1 = ((const float4*)src)[1];
        __half2 o[4];
        o[0] = __float22half2_rn(make_float2(v0.x, v0.y));
        o[1] = __float22half2_rn(make_float2(v0.z, v0.w));
        o[2] = __float22half2_rn(make_float2(v1.x, v1.y));
        o[3] = __float22half2_rn(make_float2(v1.z, v1.w));
        ((uint4*)g_A)[i] = *(uint4*)o;
    }
}

// transpose + convert: g_Wt[g][n][k] = half(W_g[k][n])
__global__ void prep_weights_kernel(const float* __restrict__ Wr,
                                    const float* __restrict__ Wz,
                                    const float* __restrict__ Wh)
{
    __shared__ float t[32][33];
    const float* src = (blockIdx.z == 0) ? Wr : (blockIdx.z == 1) ? Wz : Wh;
    __half* dst = g_Wt[blockIdx.z];
    int tx = threadIdx.x, ty = threadIdx.y;
    int c0 = blockIdx.x * 32;   // n
    int r0 = blockIdx.y * 32;   // k
    #pragma unroll
    for (int j = 0; j < 32; j += 8)
        t[ty + j][tx] = src[(size_t)(r0 + ty + j) * HID + c0 + tx];
    __syncthreads();
    #pragma unroll
    for (int j = 0; j < 32; j += 8)
        dst[(size_t)(c0 + ty + j) * KCAT + r0 + tx] = __float2half_rn(t[tx][ty + j]);
}

// ---------------------------------------------------------------------------
// Unified GEMM.  MODE 1: gates (A = g_A, stride KCAT).  MODE 2: h-tilde.
// ---------------------------------------------------------------------------
template <int MODE>
__global__ void __launch_bounds__(256, 2)
gru_gemm(const float* __restrict__ h, float* __restrict__ out)
{
    extern __shared__ char smem[];
    const uint32_t sbase = (uint32_t)__cvta_generic_to_shared(smem);
    const int tid    = threadIdx.x;
    const int lane   = tid & 31;
    const int wid    = tid >> 5;
    const int warp_m = wid >> 2;         // 0..1 -> 64-row band
    const int warp_n = wid & 3;          // 0..3 -> 32-col band

    int mat, kstart, KT, col0;
    const __half* Bmat;
    const __half* Amat;
    int astride;
    if (MODE == 1) {
        mat    = blockIdx.x >> 3;
        col0   = (blockIdx.x & 7) * BN;
        kstart = (mat == 2) ? HID : 0;
        KT     = (KCAT - kstart) / BK;   // 32 or 16
        Bmat   = g_Wt[mat];
        Amat   = g_A;  astride = KCAT;
    } else {
        mat    = 0;
        col0   = blockIdx.x * BN;
        kstart = 0;
        KT     = HID / BK;               // 16
        Bmat   = g_Wt[2];
        Amat   = g_rh; astride = HID;
    }
    const int row0 = blockIdx.y * BM;

    auto load_stage = [&](int kt) {
        const uint32_t so = sbase + (kt % NST) * STAGE_B;
        const int kbase = kstart + kt * BK;
        #pragma unroll
        for (int j = 0; j < 4; j++) {        // A: 128 rows x 8 16B-chunks
            int idx = tid + j * 256;
            int r = idx >> 3, c = idx & 7;
            cp16(so + r * (RS * 2) + c * 16,
                 Amat + (size_t)(row0 + r) * astride + kbase + c * 8);
        }
        #pragma unroll
        for (int j = 0; j < 4; j++) {        // B: 128 n-rows x 8 chunks
            int idx = tid + j * 256;
            int r = idx >> 3, c = idx & 7;
            cp16(so + A_STAGE_B + r * (RS * 2) + c * 16,
                 Bmat + (size_t)(col0 + r) * KCAT + kbase + c * 8);
        }
        cp_commit();
    };

    // per-thread ldmatrix base offsets (bytes within stage)
    uint32_t a_off[4];
    #pragma unroll
    for (int mt = 0; mt < 4; mt++)
        a_off[mt] = (warp_m * 64 + mt * 16 + (lane & 15)) * (RS * 2)
                  + ((lane >> 4) & 1) * 16;
    uint32_t b_off[2];
    #pragma unroll
    for (int nt2 = 0; nt2 < 2; nt2++)
        b_off[nt2] = A_STAGE_B
                   + (warp_n * 32 + nt2 * 16 + (lane & 7) + ((lane >> 4) & 1) * 8) * (RS * 2)
                   + ((lane >> 3) & 1) * 16;

    float acc[4][4][4];
    #pragma unroll
    for (int mt = 0; mt < 4; mt++)
        #pragma unroll
        for (int nt = 0; nt < 4; nt++)
            #pragma unroll
            for (int i = 0; i < 4; i++)
                acc[mt][nt][i] = 0.0f;

    load_stage(0);
    load_stage(1);

    for (int kt = 0; kt < KT; kt++) {
        if (kt < KT - 1) cp_wait<1>(); else cp_wait<0>();
        __syncthreads();                 // single barrier per iteration
        if (kt + 2 < KT) load_stage(kt + 2);

        const uint32_t so = sbase + (kt % NST) * STAGE_B;
        #pragma unroll
        for (int ks = 0; ks < 4; ks++) {     // four k16 steps per stage
            uint32_t a[4][4], b[2][4];
            #pragma unroll
            for (int mt = 0; mt < 4; mt++)
                ldsm4(a[mt], so + a_off[mt] + ks * 32);
            #pragma unroll
            for (int nt2 = 0; nt2 < 2; nt2++)
                ldsm4(b[nt2], so + b_off[nt2] + ks * 32);
            #pragma unroll
            for (int mt = 0; mt < 4; mt++)
                #pragma unroll
                for (int nt = 0; nt < 4; nt++)
                    mma_f16(acc[mt][nt], a[mt], &b[nt >> 1][(nt & 1) * 2]);
        }
        // NOTE: no trailing barrier — ring depth 3 means the next write to this
        // stage happens only after the next top-of-loop barrier (proof in R6 notes).
    }

    // ---- epilogue ----
    #pragma unroll
    for (int mt = 0; mt < 4; mt++) {
        #pragma unroll
        for (int nt = 0; nt < 4; nt++) {
            int r = row0 + warp_m * 64 + mt * 16 + (lane >> 2);
            int c = col0 + warp_n * 32 + nt * 8 + (lane & 3) * 2;
            #pragma unroll
            for (int half_i = 0; half_i < 2; half_i++) {
                int rr = r + half_i * 8;
                size_t gi = (size_t)rr * HID + c;
                float v0 = acc[mt][nt][half_i * 2 + 0];
                float v1 = acc[mt][nt][half_i * 2 + 1];
                if (MODE == 1) {
                    if (mat == 0) {
                        float2 hv = *(const float2*)(h + gi);
                        __half2 o = __float22half2_rn(make_float2(
                            sigmoidf_fast(v0) * hv.x, sigmoidf_fast(v1) * hv.y));
                        *(__half2*)(g_rh + gi) = o;
                    } else if (mat == 1) {
                        float2 o = make_float2(sigmoidf_fast(v0), sigmoidf_fast(v1));
                        *(float2*)(g_z + gi) = o;
                    } else {
                        *(float2*)(g_hp + gi) = make_float2(v0, v1);
                    }
                } else {
                    float2 hp2 = *(const float2*)(g_hp + gi);
                    float2 z2  = *(const float2*)(g_z  + gi);
                    float2 hv2 = *(const float2*)(h    + gi);
                    float t0 = tanhf(v0 + hp2.x);
                    float t1 = tanhf(v1 + hp2.y);
                    float2 o;
                    o.x = hv2.x + z2.x * (t0 - hv2.x);
                    o.y = hv2.y + z2.y * (t1 - hv2.y);
                    *(float2*)(out + gi) = o;
                }
            }
        }
    }
}

// ---------------------------------------------------------------------------

extern "C" void kernel_launch(void* const* d_in, const int* in_sizes, int n_in,
                              void* d_out, int out_size)
{
    const float* h  = (const float*)d_in[0];
    const float* x  = (const float*)d_in[1];
    const float* Wr = (const float*)d_in[2];
    const float* Wz = (const float*)d_in[3];
    const float* Wh = (const float*)d_in[4];
    float* out = (float*)d_out;

    cudaFuncSetAttribute(gru_gemm<1>, cudaFuncAttributeMaxDynamicSharedMemorySize, SMEM_TOTAL);
    cudaFuncSetAttribute(gru_gemm<2>, cudaFuncAttributeMaxDynamicSharedMemorySize, SMEM_TOTAL);

    prep_concat_kernel <<<2048, 256>>>(h, x);
    dim3 gT(HID / 32, KCAT / 32, 3);
    prep_weights_kernel<<<gT, dim3(32, 8)>>>(Wr, Wz, Wh);

    // Phase 1: x-fastest raster -> the 24 column-CTAs of one row panel share A in L2.
    dim3 g1(24, BATCH / BM);
    gru_gemm<1><<<g1, 256, SMEM_TOTAL>>>(h, out);

    dim3 g2(HID / BN, BATCH / BM);   // (8, 128)
    gru_gemm<2><<<g2, 256, SMEM_TOTAL>>>(h, out);
}